// round 6
// baseline (speedup 1.0000x reference)
#include <cuda_runtime.h>

// RNN: h_{s+1} = tanh(X[s]*W_ih^T + b_ih + b_hh + h_s @ W_hh^T); y_s = h_{s+1}·W_out + b_out
// SEQ=512, BATCH=4096, IN_DIM=1, HID=30.
//
// R6 changes vs R5 (200us, LDS-issue-bound: 120 LDS.64/step/SMSP x 4cyc floor):
// - h pairs loaded as LDS.128 (ulonglong2): 15 wide loads/step, operands land
//   directly in FFMA2 register pairs (no pack MOVs).
// - tanh input scale 2*log2(e) pre-folded into W_hh/W_ih/bias for lanes<30
//   (lane 30 = readout row stays unscaled) -> tanh = 1 - 2*rcp(ex2(acc)+1),
//   packed: 1 add2 + 1 fma2 + 2 ex2 + 2 rcp per batch-pair.
// - pointer-advanced X/Y addressing, pointer-swapped double buffer.
// Layout (unchanged): lane j<30 owns scaled W_hh row j as f32x2; lane 30 owns
// W_out/b_out so the readout comes out of the same matvec (acc at step s is
// y[s-1]; stored shifted, epilogue emits y[SEQ-1]).

#define SEQ   512
#define BATCH 4096
#define HID   30

typedef unsigned long long u64;

__device__ __forceinline__ u64 pack2(float lo, float hi) {
    u64 r;
    asm("mov.b64 %0, {%1, %2};" : "=l"(r) : "f"(lo), "f"(hi));
    return r;
}
__device__ __forceinline__ void unpack2(u64 v, float& a, float& b) {
    asm("mov.b64 {%0, %1}, %2;" : "=f"(a), "=f"(b) : "l"(v));
}
__device__ __forceinline__ u64 fma2(u64 a, u64 b, u64 c) {
    u64 d;
    asm("fma.rn.f32x2 %0, %1, %2, %3;" : "=l"(d) : "l"(a), "l"(b), "l"(c));
    return d;
}
__device__ __forceinline__ u64 add2(u64 a, u64 b) {
    u64 d;
    asm("add.rn.f32x2 %0, %1, %2;" : "=l"(d) : "l"(a), "l"(b));
    return d;
}
__device__ __forceinline__ float ex2f(float x) {
    float t; asm("ex2.approx.f32 %0, %1;" : "=f"(t) : "f"(x)); return t;
}
__device__ __forceinline__ float rcpf(float x) {
    float t; asm("rcp.approx.f32 %0, %1;" : "=f"(t) : "f"(x)); return t;
}

__global__ void __launch_bounds__(512) rnn_tanh_kernel(
    const float* __restrict__ X,      // [SEQ, BATCH]
    const float* __restrict__ W_ih,   // [HID, 1]
    const float* __restrict__ W_hh,   // [HID, HID]
    const float* __restrict__ b_ih,   // [HID]
    const float* __restrict__ b_hh,   // [HID]
    const float* __restrict__ W_out,  // [1, HID]
    const float* __restrict__ b_out,  // [1]
    float* __restrict__ Y)            // [SEQ, BATCH]
{
    // 16 warps/block; warp owns batch pair {2gw, 2gw+1}. h state double-buffered
    // as u64 pairs, 16B-aligned so pairs of hidden units load as LDS.128.
    __shared__ __align__(16) u64 hbuf[16][2][32];

    const int lane = threadIdx.x & 31;
    const int wip  = threadIdx.x >> 5;
    const int gw   = blockIdx.x * 16 + wip;

    const float LOG2E2 = 2.8853900817779268f;   // 2*log2(e)

    // Per-lane weight row replicated into both f32x2 halves.
    // Lanes < 30: pre-scaled by 2*log2(e) so ex2(acc) == exp(2*preact).
    u64 Wrep[HID];
    float wih = 0.0f, bias = 0.0f;
    if (lane < HID) {
        #pragma unroll
        for (int i = 0; i < HID; i++) {
            float w = W_hh[lane * HID + i] * LOG2E2;
            Wrep[i] = pack2(w, w);
        }
        wih  = W_ih[lane] * LOG2E2;
        bias = (b_ih[lane] + b_hh[lane]) * LOG2E2;
    } else if (lane == HID) {
        #pragma unroll
        for (int i = 0; i < HID; i++) {
            float w = W_out[i];
            Wrep[i] = pack2(w, w);
        }
        bias = b_out[0];
    } else {
        #pragma unroll
        for (int i = 0; i < HID; i++) Wrep[i] = 0ull;
    }
    const u64 bias2 = pack2(bias, bias);
    const u64 wih2  = pack2(wih, wih);
    const u64 ONE2  = pack2(1.0f, 1.0f);
    const u64 M2    = pack2(-2.0f, -2.0f);

    u64* hA = &hbuf[wip][0][0];
    u64* hB = &hbuf[wip][1][0];
    if (lane < HID) hA[lane] = 0ull;
    __syncwarp();

    const int ST = BATCH / 2;                        // u64 stride per step
    const u64* __restrict__ xp = reinterpret_cast<const u64*>(X) + gw;
    u64* __restrict__       yp = reinterpret_cast<u64*>(Y) + gw;
    const u64* __restrict__ xpre = xp + 2 * ST;      // prefetch cursor (s+2)

    u64 x0 = xp[0];
    u64 x1 = xp[ST];

    for (int s = 0; s < SEQ; ++s) {
        const u64 x_cur = x0;
        x0 = x1;
        if (s + 2 < SEQ) { x1 = *xpre; xpre += ST; }

        // 30-term dot product: 15 LDS.128, two independent FFMA2 chains.
        const ulonglong2* __restrict__ hp = reinterpret_cast<const ulonglong2*>(hA);
        u64 acc_a = bias2;
        u64 acc_b = fma2(x_cur, wih2, 0ull);         // wih=0 on lanes >= 30
        #pragma unroll
        for (int i = 0; i < 15; i++) {
            ulonglong2 hv = hp[i];                   // h[2i], h[2i+1]
            acc_a = fma2(hv.x, Wrep[2 * i],     acc_a);
            acc_b = fma2(hv.y, Wrep[2 * i + 1], acc_b);
        }
        const u64 acc = add2(acc_a, acc_b);

        // Lane 30 (unscaled row) holds y[s-1] = W_out·h_in + b_out.
        if (lane == HID && s > 0) yp[(s - 1) * ST] = acc;

        // tanh pair: t = 1 - 2/(ex2(acc)+1)   (acc already scaled by 2log2e)
        float a0, a1;
        unpack2(acc, a0, a1);
        const u64 ep = pack2(ex2f(a0), ex2f(a1));
        const u64 dp = add2(ep, ONE2);
        float d0, d1;
        unpack2(dp, d0, d1);
        const u64 rp = pack2(rcpf(d0), rcpf(d1));
        const u64 t  = fma2(rp, M2, ONE2);

        if (lane < HID) hB[lane] = t;
        __syncwarp();
        u64* tmp = hA; hA = hB; hB = tmp;
    }

    // Epilogue: y[SEQ-1] from the final state (lane 30's row is unscaled).
    {
        const ulonglong2* __restrict__ hp = reinterpret_cast<const ulonglong2*>(hA);
        u64 acc_a = bias2, acc_b = 0ull;
        #pragma unroll
        for (int i = 0; i < 15; i++) {
            ulonglong2 hv = hp[i];
            acc_a = fma2(hv.x, Wrep[2 * i],     acc_a);
            acc_b = fma2(hv.y, Wrep[2 * i + 1], acc_b);
        }
        if (lane == HID) yp[(SEQ - 1) * ST] = add2(acc_a, acc_b);
    }
}

extern "C" void kernel_launch(void* const* d_in, const int* in_sizes, int n_in,
                              void* d_out, int out_size) {
    const float* X     = (const float*)d_in[0];
    const float* W_ih  = (const float*)d_in[1];
    const float* W_hh  = (const float*)d_in[2];
    const float* b_ih  = (const float*)d_in[3];
    const float* b_hh  = (const float*)d_in[4];
    const float* W_out = (const float*)d_in[5];
    const float* b_out = (const float*)d_in[6];
    float* Y = (float*)d_out;

    // 2048 warps / 16 per block = 128 blocks of 512 threads: one block per SM,
    // uniform 4 warps/SMSP.
    rnn_tanh_kernel<<<128, 512>>>(X, W_ih, W_hh, b_ih, b_hh, W_out, b_out, Y);
}

// round 7
// speedup vs baseline: 1.0473x; 1.0473x over previous
#include <cuda_runtime.h>

// RNN: h_{s+1} = tanh(X[s]*W_ih^T + b_ih + b_hh + h_s @ W_hh^T); y_s = h_{s+1}·W_out + b_out
// SEQ=512, BATCH=4096, IN_DIM=1, HID=30.
//
// R7 design ("K-packed f32x2, one elem per warp"):
// Previous rounds were latency-bound at occ=25% (regs=98, of which 60 = batch-
// replicated weight pairs). New packing puts the f32x2 across ADJACENT K-terms:
//   lane j: pre[j] = hsum( sum_i fma2((h[2i],h[2i+1]), (W[j][2i],W[j][2i+1])) )
// -> 15 weight u64s = 30 regs, 15 fma2 (half the FMA instrs), 8 LDS.128.
// One batch elem per warp -> 4096 warps, 256 blocks x 512thr, 2 blocks/SM
// (launch_bounds(512,2) caps regs at 64) = 8 warps/SMSP, occ 50%.
// - lane 30 owns W_out/b_out (unscaled): its pre IS y[s-1]; stored shifted,
//   epilogue emits y[SEQ-1]. Lanes 0..29 weights pre-scaled by 2*log2(e) so
//   tanh = 1 - 2*rcp(ex2(acc)+1) with scalar MUFU chain (no pack/unpack MOVs).

#define SEQ   512
#define BATCH 4096
#define HID   30

typedef unsigned long long u64;

__device__ __forceinline__ u64 pack2(float lo, float hi) {
    u64 r;
    asm("mov.b64 %0, {%1, %2};" : "=l"(r) : "f"(lo), "f"(hi));
    return r;
}
__device__ __forceinline__ void unpack2(u64 v, float& a, float& b) {
    asm("mov.b64 {%0, %1}, %2;" : "=f"(a), "=f"(b) : "l"(v));
}
__device__ __forceinline__ u64 fma2(u64 a, u64 b, u64 c) {
    u64 d;
    asm("fma.rn.f32x2 %0, %1, %2, %3;" : "=l"(d) : "l"(a), "l"(b), "l"(c));
    return d;
}
__device__ __forceinline__ float ex2f(float x) {
    float t; asm("ex2.approx.f32 %0, %1;" : "=f"(t) : "f"(x)); return t;
}
__device__ __forceinline__ float rcpf(float x) {
    float t; asm("rcp.approx.f32 %0, %1;" : "=f"(t) : "f"(x)); return t;
}

__global__ void __launch_bounds__(512, 2) rnn_tanh_kernel(
    const float* __restrict__ X,      // [SEQ, BATCH]
    const float* __restrict__ W_ih,   // [HID, 1]
    const float* __restrict__ W_hh,   // [HID, HID]
    const float* __restrict__ b_ih,   // [HID]
    const float* __restrict__ b_hh,   // [HID]
    const float* __restrict__ W_out,  // [1, HID]
    const float* __restrict__ b_out,  // [1]
    float* __restrict__ Y)            // [SEQ, BATCH]
{
    // 16 warps/block, ONE batch elem per warp. h double-buffered per warp,
    // 32 floats (2 pad), 16B-aligned for LDS.128 broadcast.
    __shared__ __align__(16) float hbuf[16][2][32];

    const int lane = threadIdx.x & 31;
    const int wip  = threadIdx.x >> 5;
    const int gw   = blockIdx.x * 16 + wip;          // batch index

    const float LOG2E2 = 2.8853900817779268f;        // 2*log2(e)

    // Lane j holds row j packed over K-pairs: Wp[i] = (W[j][2i], W[j][2i+1]).
    u64 Wp[15];
    float wih = 0.0f, bias = 0.0f;
    if (lane < HID) {
        #pragma unroll
        for (int i = 0; i < 15; i++) {
            float w0 = W_hh[lane * HID + 2 * i]     * LOG2E2;
            float w1 = W_hh[lane * HID + 2 * i + 1] * LOG2E2;
            Wp[i] = pack2(w0, w1);
        }
        wih  = W_ih[lane] * LOG2E2;
        bias = (b_ih[lane] + b_hh[lane]) * LOG2E2;
    } else if (lane == HID) {
        #pragma unroll
        for (int i = 0; i < 15; i++)
            Wp[i] = pack2(W_out[2 * i], W_out[2 * i + 1]);
        bias = b_out[0];
    } else {
        #pragma unroll
        for (int i = 0; i < 15; i++) Wp[i] = 0ull;
    }

    hbuf[wip][0][lane] = 0.0f;   // all 32 lanes (pads too)
    hbuf[wip][1][lane] = 0.0f;
    __syncwarp();

    const float* __restrict__ xp = X + gw;
    float* __restrict__       yw = Y + gw;           // moving cursor for y[s-1]

    float x0 = xp[0];
    float x1 = xp[BATCH];
    const float* xpre = xp + 2 * BATCH;

    int cur = 0;
    for (int s = 0; s < SEQ; ++s) {
        const float x_cur = x0;
        x0 = x1;
        if (s + 2 < SEQ) { x1 = *xpre; xpre += BATCH; }

        // 8 LDS.128 broadcasts of h; two independent fma2 chains (8 + 7 terms).
        const ulonglong2* __restrict__ hp =
            reinterpret_cast<const ulonglong2*>(&hbuf[wip][cur][0]);
        u64 acc_a = 0ull, acc_b = 0ull;
        #pragma unroll
        for (int i = 0; i < 8; i++) {
            ulonglong2 hv = hp[i];                   // (h[4i],h[4i+1]),(h[4i+2],h[4i+3])
            acc_a = fma2(hv.x, Wp[2 * i], acc_a);    // pairs 0,2,...,14
            if (i < 7) acc_b = fma2(hv.y, Wp[2 * i + 1], acc_b); // pairs 1,...,13
        }
        float a0, a1, b0v, b1v;
        unpack2(acc_a, a0, a1);
        unpack2(acc_b, b0v, b1v);
        // pre = bias + x*wih + sum of all four partial lanes
        const float pre = __fmaf_rn(x_cur, wih, bias + ((a0 + a1) + (b0v + b1v)));

        // Lane 30 (unscaled readout row): pre == y[s-1].
        if (lane == HID && s > 0) { yw[0] = pre; yw += BATCH; }

        // tanh (input pre-scaled by 2*log2(e) for lanes<30): 1 - 2/(ex2+1)
        const float e = ex2f(pre);
        const float r = rcpf(e + 1.0f);
        const float t = __fmaf_rn(-2.0f, r, 1.0f);

        cur ^= 1;
        if (lane < HID) hbuf[wip][cur][lane] = t;
        __syncwarp();
    }

    // Epilogue: y[SEQ-1] from the final state.
    {
        const ulonglong2* __restrict__ hp =
            reinterpret_cast<const ulonglong2*>(&hbuf[wip][cur][0]);
        u64 acc_a = 0ull, acc_b = 0ull;
        #pragma unroll
        for (int i = 0; i < 8; i++) {
            ulonglong2 hv = hp[i];
            acc_a = fma2(hv.x, Wp[2 * i], acc_a);
            if (i < 7) acc_b = fma2(hv.y, Wp[2 * i + 1], acc_b);
        }
        if (lane == HID) {
            float a0, a1, b0v, b1v;
            unpack2(acc_a, a0, a1);
            unpack2(acc_b, b0v, b1v);
            yw[0] = bias + ((a0 + a1) + (b0v + b1v));
        }
    }
}

extern "C" void kernel_launch(void* const* d_in, const int* in_sizes, int n_in,
                              void* d_out, int out_size) {
    const float* X     = (const float*)d_in[0];
    const float* W_ih  = (const float*)d_in[1];
    const float* W_hh  = (const float*)d_in[2];
    const float* b_ih  = (const float*)d_in[3];
    const float* b_hh  = (const float*)d_in[4];
    const float* W_out = (const float*)d_in[5];
    const float* b_out = (const float*)d_in[6];
    float* Y = (float*)d_out;

    // 4096 warps (1 batch elem each) / 16 per block = 256 blocks of 512 thr;
    // launch_bounds(512,2) -> 2 blocks/SM on 128 SMs, 8 warps/SMSP, occ 50%.
    rnn_tanh_kernel<<<BATCH / 16, 512>>>(X, W_ih, W_hh, b_ih, b_hh, W_out, b_out, Y);
}

// round 8
// speedup vs baseline: 1.0953x; 1.0458x over previous
#include <cuda_runtime.h>

// RNN: h_{s+1} = tanh(X[s]*W_ih^T + b_ih + b_hh + h_s @ W_hh^T); y_s = h_{s+1}·W_out + b_out
// SEQ=512, BATCH=4096, IN_DIM=1, HID=30.
//
// R8: "2 rows per lane, 2 elems per warp" — attacks the smem crossbar, which
// R5/R6/R7 all saturated at ~4KB/elem-step (every lane read the full 120B h).
// New: lanes 0-15 = elem A, lanes 16-31 = elem B; lane r(=lane&15) owns rows
// {2r, 2r+1} with K-packed f32x2 weights; r=15 owns the W_out readout row +
// a zero dummy row. Each lane reads only ITS elem's h (8 LDS.128 = 128B), so
// the warp's 4KB crossbar traffic now serves 2 elems -> 16cy/elem (was 30).
// h written back as one STS.64 (t0,t1) = exactly the K-pair layout read next.
// 2048 warps in 64-thr blocks -> 1024 blocks over all 148 SMs (R7 idled 20).
// Readout: r=15's pre0 at step s IS y[s-1] (shift-store + epilogue, proven).
// Lanes<15 weights pre-scaled by 2*log2(e): tanh = 1 - 2*rcp(ex2(acc)+1).

#define SEQ   512
#define BATCH 4096
#define HID   30

typedef unsigned long long u64;

__device__ __forceinline__ u64 pack2(float lo, float hi) {
    u64 r;
    asm("mov.b64 %0, {%1, %2};" : "=l"(r) : "f"(lo), "f"(hi));
    return r;
}
__device__ __forceinline__ void unpack2(u64 v, float& a, float& b) {
    asm("mov.b64 {%0, %1}, %2;" : "=f"(a), "=f"(b) : "l"(v));
}
__device__ __forceinline__ u64 fma2(u64 a, u64 b, u64 c) {
    u64 d;
    asm("fma.rn.f32x2 %0, %1, %2, %3;" : "=l"(d) : "l"(a), "l"(b), "l"(c));
    return d;
}
__device__ __forceinline__ u64 add2(u64 a, u64 b) {
    u64 d;
    asm("add.rn.f32x2 %0, %1, %2;" : "=l"(d) : "l"(a), "l"(b));
    return d;
}
__device__ __forceinline__ float ex2f(float x) {
    float t; asm("ex2.approx.f32 %0, %1;" : "=f"(t) : "f"(x)); return t;
}
__device__ __forceinline__ float rcpf(float x) {
    float t; asm("rcp.approx.f32 %0, %1;" : "=f"(t) : "f"(x)); return t;
}

__global__ void __launch_bounds__(64) rnn_tanh_kernel(
    const float* __restrict__ X,      // [SEQ, BATCH]
    const float* __restrict__ W_ih,   // [HID, 1]
    const float* __restrict__ W_hh,   // [HID, HID]
    const float* __restrict__ b_ih,   // [HID]
    const float* __restrict__ b_hh,   // [HID]
    const float* __restrict__ W_out,  // [1, HID]
    const float* __restrict__ b_out,  // [1]
    float* __restrict__ Y)            // [SEQ, BATCH]
{
    // [warp][buf][elem-half][K-pair]; 16 pairs = 128B row, pair 15 is zero pad.
    __shared__ __align__(16) u64 hbuf[2][2][2][16];

    const int lane  = threadIdx.x & 31;
    const int wip   = threadIdx.x >> 5;          // 0..1
    const int gw    = blockIdx.x * 2 + wip;      // 0..2047
    const int r     = lane & 15;                 // row-slot within half-warp
    const int ehalf = lane >> 4;                 // which batch elem of the pair

    const float C = 2.8853900817779268f;         // 2*log2(e)

    // Lane's two rows, K-packed: Wk[i] = (W[row][2i], W[row][2i+1]); index 15 = 0 pad.
    u64 W0[16], W1[16];
    float bias0 = 0.f, bias1 = 0.f, wih0 = 0.f, wih1 = 0.f;
    if (r < 15) {
        const int R0 = 2 * r, R1 = 2 * r + 1;
        #pragma unroll
        for (int k = 0; k < 15; k++) {
            W0[k] = pack2(W_hh[R0 * HID + 2 * k] * C, W_hh[R0 * HID + 2 * k + 1] * C);
            W1[k] = pack2(W_hh[R1 * HID + 2 * k] * C, W_hh[R1 * HID + 2 * k + 1] * C);
        }
        W0[15] = 0ull; W1[15] = 0ull;
        wih0  = W_ih[R0] * C;            wih1  = W_ih[R1] * C;
        bias0 = (b_ih[R0] + b_hh[R0]) * C; bias1 = (b_ih[R1] + b_hh[R1]) * C;
    } else {
        // r == 15: row0 = readout (unscaled W_out/b_out), row1 = dummy zero.
        #pragma unroll
        for (int k = 0; k < 15; k++) {
            W0[k] = pack2(W_out[2 * k], W_out[2 * k + 1]);
            W1[k] = 0ull;
        }
        W0[15] = 0ull; W1[15] = 0ull;
        bias0 = b_out[0];
    }

    // Zero h (both buffers, incl. pad pair written by r==15, never overwritten).
    hbuf[wip][0][ehalf][r] = 0ull;
    hbuf[wip][1][ehalf][r] = 0ull;
    __syncwarp();

    const int ST64 = BATCH / 2;                       // u64 stride per step
    const u64* __restrict__ xq = reinterpret_cast<const u64*>(X) + gw; // (x_2gw, x_2gw+1)
    const int e = 2 * gw + ehalf;                     // this lane's batch elem
    float* __restrict__ ym = Y + e;                   // moving cursor: y[s-1]

    // X prefetch, depth 3 (uniform-address LDG.64, one sector per warp).
    u64 x_d0 = xq[0];
    u64 x_d1 = xq[ST64];
    u64 x_d2 = xq[2 * ST64];
    const u64* xpre = xq + 3 * ST64;

    int cur = 0;
    for (int s = 0; s < SEQ; ++s) {
        const u64 xcur = x_d0;
        x_d0 = x_d1; x_d1 = x_d2;
        if (s + 3 < SEQ) { x_d2 = *xpre; xpre += ST64; }
        float xlo, xhi;
        unpack2(xcur, xlo, xhi);
        const float x = ehalf ? xhi : xlo;

        // 8 LDS.128 of THIS elem's h; 4 independent fma2 chains (2 rows x 2).
        const ulonglong2* __restrict__ hp =
            reinterpret_cast<const ulonglong2*>(&hbuf[wip][cur][ehalf][0]);
        u64 c0a = pack2(bias0, 0.f), c0b = 0ull;
        u64 c1a = pack2(bias1, 0.f), c1b = 0ull;
        #pragma unroll
        for (int i = 0; i < 8; i++) {
            ulonglong2 hv = hp[i];                    // K-pairs 2i, 2i+1
            c0a = fma2(hv.x, W0[2 * i],     c0a);
            c0b = fma2(hv.y, W0[2 * i + 1], c0b);
            c1a = fma2(hv.x, W1[2 * i],     c1a);
            c1b = fma2(hv.y, W1[2 * i + 1], c1b);
        }
        const u64 s0 = add2(c0a, c0b);
        const u64 s1 = add2(c1a, c1b);
        float u, v, w, z;
        unpack2(s0, u, v);
        unpack2(s1, w, z);
        const float pre0 = __fmaf_rn(x, wih0, u + v);
        const float pre1 = __fmaf_rn(x, wih1, w + z);

        // Readout lane: pre0 == y[s-1] (consumed the state entering step s).
        if (s > 0) {
            if (r == 15) *ym = pre0;
            ym += BATCH;
        }

        // tanh (inputs pre-scaled by 2log2e on real rows): 1 - 2/(ex2+1).
        const float t0 = __fmaf_rn(-2.f, rcpf(ex2f(pre0) + 1.f), 1.f);
        const float t1 = __fmaf_rn(-2.f, rcpf(ex2f(pre1) + 1.f), 1.f);

        cur ^= 1;
        if (r < 15) hbuf[wip][cur][ehalf][r] = pack2(t0, t1);
        __syncwarp();
    }

    // Epilogue: y[SEQ-1] from the final state (ym now points at row SEQ-1).
    {
        const ulonglong2* __restrict__ hp =
            reinterpret_cast<const ulonglong2*>(&hbuf[wip][cur][ehalf][0]);
        u64 c0a = pack2(bias0, 0.f), c0b = 0ull;
        #pragma unroll
        for (int i = 0; i < 8; i++) {
            ulonglong2 hv = hp[i];
            c0a = fma2(hv.x, W0[2 * i],     c0a);
            c0b = fma2(hv.y, W0[2 * i + 1], c0b);
        }
        if (r == 15) {
            float u, v;
            unpack2(add2(c0a, c0b), u, v);
            *ym = u + v;
        }
    }
}

extern "C" void kernel_launch(void* const* d_in, const int* in_sizes, int n_in,
                              void* d_out, int out_size) {
    const float* X     = (const float*)d_in[0];
    const float* W_ih  = (const float*)d_in[1];
    const float* W_hh  = (const float*)d_in[2];
    const float* b_ih  = (const float*)d_in[3];
    const float* b_hh  = (const float*)d_in[4];
    const float* W_out = (const float*)d_in[5];
    const float* b_out = (const float*)d_in[6];
    float* Y = (float*)d_out;

    // 2048 warps (2 elems each) in 64-thread blocks: 1024 blocks spread over
    // all 148 SMs (6-7 blocks/SM, ~1.4% imbalance).
    rnn_tanh_kernel<<<1024, 64>>>(X, W_ih, W_hh, b_ih, b_hh, W_out, b_out, Y);
}

// round 9
// speedup vs baseline: 1.1436x; 1.0441x over previous
#include <cuda_runtime.h>

// RNN: h_{s+1} = tanh(X[s]*W_ih^T + b_ih + b_hh + h_s @ W_hh^T); y_s = h_{s+1}·W_out + b_out
// SEQ=512, BATCH=4096, IN_DIM=1, HID=30.
//
// R9 = R8 layout (lanes 0-15 elem A / 16-31 elem B; lane r owns rows {2r,2r+1}
// K-packed f32x2; r=15 owns W_out readout row) with a BRANCH-FREE loop body.
// R8's gap to model (~400cy/step vs ~190 static chain) was ptxas BSSY/BSYNC
// pairs (33-56cy each) for the 3 ifs in the body. Changes:
//  - y[s-1] store: inline-asm predicated @q st.global.f32 (no BSSY).
//  - STS unconditional: r==15 writes pad pair 15; multiplied by zero weights.
//  - X prefetch: clamped index min(s+3,SEQ-1) + unconditional LDG (no branch).
//  - per-lane scalar X loads; #pragma unroll 2 folds buffer parity.
// Readout trick unchanged: r=15's pre0 at step s IS y[s-1]; epilogue emits
// y[SEQ-1]. Real rows pre-scaled by 2*log2(e): tanh = 1 - 2*rcp(ex2(acc)+1).

#define SEQ   512
#define BATCH 4096
#define HID   30

typedef unsigned long long u64;

__device__ __forceinline__ u64 pack2(float lo, float hi) {
    u64 r;
    asm("mov.b64 %0, {%1, %2};" : "=l"(r) : "f"(lo), "f"(hi));
    return r;
}
__device__ __forceinline__ void unpack2(u64 v, float& a, float& b) {
    asm("mov.b64 {%0, %1}, %2;" : "=f"(a), "=f"(b) : "l"(v));
}
__device__ __forceinline__ u64 fma2(u64 a, u64 b, u64 c) {
    u64 d;
    asm("fma.rn.f32x2 %0, %1, %2, %3;" : "=l"(d) : "l"(a), "l"(b), "l"(c));
    return d;
}
__device__ __forceinline__ u64 add2(u64 a, u64 b) {
    u64 d;
    asm("add.rn.f32x2 %0, %1, %2;" : "=l"(d) : "l"(a), "l"(b));
    return d;
}
__device__ __forceinline__ float ex2f(float x) {
    float t; asm("ex2.approx.f32 %0, %1;" : "=f"(t) : "f"(x)); return t;
}
__device__ __forceinline__ float rcpf(float x) {
    float t; asm("rcp.approx.f32 %0, %1;" : "=f"(t) : "f"(x)); return t;
}
// Predicated store: guaranteed @q STG, no BSSY/BSYNC convergence stack.
__device__ __forceinline__ void st_pred(unsigned p, float* ptr, float v) {
    asm volatile("{\n\t.reg .pred q;\n\tsetp.ne.u32 q, %0, 0;\n\t"
                 "@q st.global.f32 [%1], %2;\n\t}"
                 :: "r"(p), "l"(ptr), "f"(v) : "memory");
}

__global__ void __launch_bounds__(64) rnn_tanh_kernel(
    const float* __restrict__ X,      // [SEQ, BATCH]
    const float* __restrict__ W_ih,   // [HID, 1]
    const float* __restrict__ W_hh,   // [HID, HID]
    const float* __restrict__ b_ih,   // [HID]
    const float* __restrict__ b_hh,   // [HID]
    const float* __restrict__ W_out,  // [1, HID]
    const float* __restrict__ b_out,  // [1]
    float* __restrict__ Y)            // [SEQ, BATCH]
{
    // [warp][buf][elem-half][K-pair]; pair 15 = pad (zero weights multiply it).
    __shared__ __align__(16) u64 hbuf[2][2][2][16];

    const int lane  = threadIdx.x & 31;
    const int wip   = threadIdx.x >> 5;
    const int gw    = blockIdx.x * 2 + wip;      // 0..2047
    const int r     = lane & 15;
    const int ehalf = lane >> 4;

    const float C = 2.8853900817779268f;         // 2*log2(e)

    u64 W0[16], W1[16];
    float bias0 = 0.f, bias1 = 0.f, wih0 = 0.f, wih1 = 0.f;
    if (r < 15) {
        const int R0 = 2 * r, R1 = 2 * r + 1;
        #pragma unroll
        for (int k = 0; k < 15; k++) {
            W0[k] = pack2(W_hh[R0 * HID + 2 * k] * C, W_hh[R0 * HID + 2 * k + 1] * C);
            W1[k] = pack2(W_hh[R1 * HID + 2 * k] * C, W_hh[R1 * HID + 2 * k + 1] * C);
        }
        W0[15] = 0ull; W1[15] = 0ull;
        wih0  = W_ih[R0] * C;              wih1  = W_ih[R1] * C;
        bias0 = (b_ih[R0] + b_hh[R0]) * C; bias1 = (b_ih[R1] + b_hh[R1]) * C;
    } else {
        #pragma unroll
        for (int k = 0; k < 15; k++) {
            W0[k] = pack2(W_out[2 * k], W_out[2 * k + 1]);
            W1[k] = 0ull;
        }
        W0[15] = 0ull; W1[15] = 0ull;
        bias0 = b_out[0];
    }

    hbuf[wip][0][ehalf][r] = 0ull;
    hbuf[wip][1][ehalf][r] = 0ull;
    __syncwarp();

    const int e = 2 * gw + ehalf;                // this lane's batch elem
    const float* __restrict__ xp = X + e;
    float* ym = Y + e - BATCH;                   // y[s-1] cursor (s=0 masked off)
    const unsigned is_out = (r == 15) ? 1u : 0u;

    // X prefetch pipeline, depth 3 (2 distinct addrs/warp -> dedup'd LDG).
    float xf0 = xp[0];
    float xf1 = xp[BATCH];
    float xf2 = xp[2 * BATCH];

    int cur = 0;
    #pragma unroll 2
    for (int s = 0; s < SEQ; ++s) {
        const float x = xf0;
        xf0 = xf1; xf1 = xf2;
        int nidx = s + 3; nidx = nidx < SEQ - 1 ? nidx : SEQ - 1;  // clamp, no branch
        xf2 = xp[nidx * BATCH];

        // 8 LDS.128 of this elem's h; 4 independent fma2 chains (2 rows x 2).
        const ulonglong2* __restrict__ hp =
            reinterpret_cast<const ulonglong2*>(&hbuf[wip][cur][ehalf][0]);
        u64 c0a = pack2(bias0, 0.f), c0b = 0ull;
        u64 c1a = pack2(bias1, 0.f), c1b = 0ull;
        #pragma unroll
        for (int i = 0; i < 8; i++) {
            ulonglong2 hv = hp[i];
            c0a = fma2(hv.x, W0[2 * i],     c0a);
            c0b = fma2(hv.y, W0[2 * i + 1], c0b);
            c1a = fma2(hv.x, W1[2 * i],     c1a);
            c1b = fma2(hv.y, W1[2 * i + 1], c1b);
        }
        float u, v, w, z;
        unpack2(add2(c0a, c0b), u, v);
        unpack2(add2(c1a, c1b), w, z);
        const float pre0 = __fmaf_rn(x, wih0, u + v);
        const float pre1 = __fmaf_rn(x, wih1, w + z);

        // y[s-1] = pre0 on readout lanes; predicated STG, no branch.
        st_pred(is_out & (unsigned)(s > 0), ym, pre0);
        ym += BATCH;

        // tanh: inputs pre-scaled by 2log2e on real rows -> 1 - 2/(ex2+1).
        const float t0 = __fmaf_rn(-2.f, rcpf(ex2f(pre0) + 1.f), 1.f);
        const float t1 = __fmaf_rn(-2.f, rcpf(ex2f(pre1) + 1.f), 1.f);

        cur ^= 1;
        // Unconditional: r==15 writes pad pair 15 (finite garbage x zero weight).
        hbuf[wip][cur][ehalf][r] = pack2(t0, t1);
        __syncwarp();
    }

    // Epilogue: y[SEQ-1] from the final state (ym points at row SEQ-1).
    {
        const ulonglong2* __restrict__ hp =
            reinterpret_cast<const ulonglong2*>(&hbuf[wip][cur][ehalf][0]);
        u64 c0a = pack2(bias0, 0.f), c0b = 0ull;
        #pragma unroll
        for (int i = 0; i < 8; i++) {
            ulonglong2 hv = hp[i];
            c0a = fma2(hv.x, W0[2 * i],     c0a);
            c0b = fma2(hv.y, W0[2 * i + 1], c0b);
        }
        float u, v;
        unpack2(add2(c0a, c0b), u, v);
        st_pred(is_out, ym, u + v);
    }
}

extern "C" void kernel_launch(void* const* d_in, const int* in_sizes, int n_in,
                              void* d_out, int out_size) {
    const float* X     = (const float*)d_in[0];
    const float* W_ih  = (const float*)d_in[1];
    const float* W_hh  = (const float*)d_in[2];
    const float* b_ih  = (const float*)d_in[3];
    const float* b_hh  = (const float*)d_in[4];
    const float* W_out = (const float*)d_in[5];
    const float* b_out = (const float*)d_in[6];
    float* Y = (float*)d_out;

    // 2048 warps (2 elems each) in 64-thread blocks over all 148 SMs.
    rnn_tanh_kernel<<<1024, 64>>>(X, W_ih, W_hh, b_ih, b_hh, W_out, b_out, Y);
}